// round 4
// baseline (speedup 1.0000x reference)
#include <cuda_runtime.h>
#include <math.h>

#define T_TOK 524288
#define D_DIM 256
#define N_SEG 8192

__device__ __align__(16) float g_mean[N_SEG * D_DIM];
__device__ __align__(16) float g_tg[N_SEG * D_DIM];

__device__ __forceinline__ int lower_bound_dev(const int* __restrict__ a, int n, int key) {
    int lo = 0, hi = n;
    while (lo < hi) {
        int mid = (lo + hi) >> 1;
        if (__ldg(a + mid) < key) lo = mid + 1; else hi = mid;
    }
    return lo;
}

// ---------------------------------------------------------------------------
// Pass 1: per-segment mean. One block per segment. Thread owns float4 column
// (tid&63)*4 of row-group tid>>6. Manual 4-wide row batching => 4 independent
// LDG.128 in flight per thread; __ldcs (no temporal reuse).
// ---------------------------------------------------------------------------
__global__ void k_segmean(const float* __restrict__ emb, const int* __restrict__ obj) {
    int n = blockIdx.x, tid = threadIdx.x;
    __shared__ int sb[2];
    __shared__ __align__(16) float red[4][256];
    if (tid == 0)       sb[0] = lower_bound_dev(obj, T_TOK, n);
    else if (tid == 32) sb[1] = lower_bound_dev(obj, T_TOK, n + 1);
    __syncthreads();
    int s = sb[0], e = sb[1];

    int r = tid >> 6;
    int c4 = (tid & 63) * 4;
    const float4* base = (const float4*)(emb) + (c4 >> 2);

    float4 A0 = make_float4(0.f,0.f,0.f,0.f), A1 = A0, A2 = A0, A3 = A0;
    int t = s + r;
    // 16 rows per iteration (4 per thread, stride 4)
    for (; t + 12 < e; t += 16) {
        float4 v0 = __ldcs(base + (size_t)(t     ) * 64);
        float4 v1 = __ldcs(base + (size_t)(t +  4) * 64);
        float4 v2 = __ldcs(base + (size_t)(t +  8) * 64);
        float4 v3 = __ldcs(base + (size_t)(t + 12) * 64);
        A0.x += v0.x; A0.y += v0.y; A0.z += v0.z; A0.w += v0.w;
        A1.x += v1.x; A1.y += v1.y; A1.z += v1.z; A1.w += v1.w;
        A2.x += v2.x; A2.y += v2.y; A2.z += v2.z; A2.w += v2.w;
        A3.x += v3.x; A3.y += v3.y; A3.z += v3.z; A3.w += v3.w;
    }
    for (; t < e; t += 4) {
        float4 v0 = __ldcs(base + (size_t)t * 64);
        A0.x += v0.x; A0.y += v0.y; A0.z += v0.z; A0.w += v0.w;
    }
    float4 acc;
    acc.x = (A0.x + A1.x) + (A2.x + A3.x);
    acc.y = (A0.y + A1.y) + (A2.y + A3.y);
    acc.z = (A0.z + A1.z) + (A2.z + A3.z);
    acc.w = (A0.w + A1.w) + (A2.w + A3.w);
    *(float4*)&red[r][c4] = acc;
    __syncthreads();

    float sum = red[0][tid] + red[1][tid] + red[2][tid] + red[3][tid];
    g_mean[(size_t)n * D_DIM + tid] = sum / fmaxf((float)(e - s), 1.f);
}

// ---------------------------------------------------------------------------
// Pass 2: g_tg = tanh(g_mean @ W). Tiled SGEMM, BM=BN=64, BK=16, 4x4 reg tile.
// ---------------------------------------------------------------------------
__global__ void k_gemm_tanh(const float* __restrict__ W) {
    __shared__ __align__(16) float As[16][64];
    __shared__ __align__(16) float Bs[16][64];
    int tid = threadIdx.x;
    int tx = tid & 15, ty = tid >> 4;
    int bm = blockIdx.x * 64, bn = blockIdx.y * 64;

    int ar  = tid >> 2;
    int ak4 = (tid & 3) * 4;
    int br  = tid >> 4;
    int bc4 = (tid & 15) * 4;

    float acc[4][4] = {};
    for (int k0 = 0; k0 < 256; k0 += 16) {
        float4 av = *(const float4*)(g_mean + (size_t)(bm + ar) * 256 + k0 + ak4);
        float4 bv = *(const float4*)(W + (size_t)(k0 + br) * 256 + bn + bc4);
        As[ak4 + 0][ar] = av.x;
        As[ak4 + 1][ar] = av.y;
        As[ak4 + 2][ar] = av.z;
        As[ak4 + 3][ar] = av.w;
        *(float4*)&Bs[br][bc4] = bv;
        __syncthreads();
#pragma unroll
        for (int k = 0; k < 16; ++k) {
            float a[4], b[4];
            *(float4*)a = *(const float4*)&As[k][ty * 4];
            *(float4*)b = *(const float4*)&Bs[k][tx * 4];
#pragma unroll
            for (int i = 0; i < 4; ++i)
#pragma unroll
                for (int j = 0; j < 4; ++j)
                    acc[i][j] += a[i] * b[j];
        }
        __syncthreads();
    }
#pragma unroll
    for (int i = 0; i < 4; ++i) {
        float4 o;
        o.x = tanhf(acc[i][0]);
        o.y = tanhf(acc[i][1]);
        o.z = tanhf(acc[i][2]);
        o.w = tanhf(acc[i][3]);
        *(float4*)(g_tg + (size_t)(bm + ty * 4 + i) * 256 + bn + tx * 4) = o;
    }
}

// ---------------------------------------------------------------------------
// Pass 3 (fused): scores + weighted segment sum + broadcast. One block per
// segment; each warp processes FOUR tokens per iteration (independent
// dot/shfl chains interleaved); streaming loads/stores.
// ---------------------------------------------------------------------------
__global__ void k_score_rep_bcast(const float* __restrict__ emb,
                                  const int* __restrict__ obj,
                                  float* __restrict__ out) {
    int n = blockIdx.x, tid = threadIdx.x;
    __shared__ int sb[2];
    __shared__ __align__(16) float stg[256];
    __shared__ __align__(16) float srep[256];
    if (tid == 0)       sb[0] = lower_bound_dev(obj, T_TOK, n);
    else if (tid == 32) sb[1] = lower_bound_dev(obj, T_TOK, n + 1);
    stg[tid]  = g_tg[(size_t)n * 256 + tid];
    srep[tid] = 0.f;
    __syncthreads();
    int s = sb[0], e = sb[1];
    int lane = tid & 31, w = tid >> 5;

    float4 tga = *(const float4*)&stg[lane * 8];
    float4 tgb = *(const float4*)&stg[lane * 8 + 4];
    float acc[8] = {0.f,0.f,0.f,0.f,0.f,0.f,0.f,0.f};

    const float4* base = (const float4*)emb + lane * 2;   // token row base + lane*8 floats

    int t = s + 4 * w;
    for (; t + 3 < e; t += 32) {
        float4 a0 = __ldcs(base + (size_t)(t + 0) * 64);
        float4 b0 = __ldcs(base + (size_t)(t + 0) * 64 + 1);
        float4 a1 = __ldcs(base + (size_t)(t + 1) * 64);
        float4 b1 = __ldcs(base + (size_t)(t + 1) * 64 + 1);
        float4 a2 = __ldcs(base + (size_t)(t + 2) * 64);
        float4 b2 = __ldcs(base + (size_t)(t + 2) * 64 + 1);
        float4 a3 = __ldcs(base + (size_t)(t + 3) * 64);
        float4 b3 = __ldcs(base + (size_t)(t + 3) * 64 + 1);
        float d0 = a0.x*tga.x + a0.y*tga.y + a0.z*tga.z + a0.w*tga.w
                 + b0.x*tgb.x + b0.y*tgb.y + b0.z*tgb.z + b0.w*tgb.w;
        float d1 = a1.x*tga.x + a1.y*tga.y + a1.z*tga.z + a1.w*tga.w
                 + b1.x*tgb.x + b1.y*tgb.y + b1.z*tgb.z + b1.w*tgb.w;
        float d2 = a2.x*tga.x + a2.y*tga.y + a2.z*tga.z + a2.w*tga.w
                 + b2.x*tgb.x + b2.y*tgb.y + b2.z*tgb.z + b2.w*tgb.w;
        float d3 = a3.x*tga.x + a3.y*tga.y + a3.z*tga.z + a3.w*tga.w
                 + b3.x*tgb.x + b3.y*tgb.y + b3.z*tgb.z + b3.w*tgb.w;
#pragma unroll
        for (int off = 16; off; off >>= 1) {
            d0 += __shfl_xor_sync(0xffffffffu, d0, off);
            d1 += __shfl_xor_sync(0xffffffffu, d1, off);
            d2 += __shfl_xor_sync(0xffffffffu, d2, off);
            d3 += __shfl_xor_sync(0xffffffffu, d3, off);
        }
        float s0 = 1.f / (1.f + __expf(-d0));
        float s1 = 1.f / (1.f + __expf(-d1));
        float s2 = 1.f / (1.f + __expf(-d2));
        float s3 = 1.f / (1.f + __expf(-d3));
        acc[0] += (a0.x*s0 + a1.x*s1) + (a2.x*s2 + a3.x*s3);
        acc[1] += (a0.y*s0 + a1.y*s1) + (a2.y*s2 + a3.y*s3);
        acc[2] += (a0.z*s0 + a1.z*s1) + (a2.z*s2 + a3.z*s3);
        acc[3] += (a0.w*s0 + a1.w*s1) + (a2.w*s2 + a3.w*s3);
        acc[4] += (b0.x*s0 + b1.x*s1) + (b2.x*s2 + b3.x*s3);
        acc[5] += (b0.y*s0 + b1.y*s1) + (b2.y*s2 + b3.y*s3);
        acc[6] += (b0.z*s0 + b1.z*s1) + (b2.z*s2 + b3.z*s3);
        acc[7] += (b0.w*s0 + b1.w*s1) + (b2.w*s2 + b3.w*s3);
    }
    for (; t < e; ++t) {
        float4 a0 = __ldcs(base + (size_t)t * 64);
        float4 b0 = __ldcs(base + (size_t)t * 64 + 1);
        float d0 = a0.x*tga.x + a0.y*tga.y + a0.z*tga.z + a0.w*tga.w
                 + b0.x*tgb.x + b0.y*tgb.y + b0.z*tgb.z + b0.w*tgb.w;
#pragma unroll
        for (int off = 16; off; off >>= 1)
            d0 += __shfl_xor_sync(0xffffffffu, d0, off);
        float s0 = 1.f / (1.f + __expf(-d0));
        acc[0] += a0.x*s0; acc[1] += a0.y*s0;
        acc[2] += a0.z*s0; acc[3] += a0.w*s0;
        acc[4] += b0.x*s0; acc[5] += b0.y*s0;
        acc[6] += b0.z*s0; acc[7] += b0.w*s0;
    }
#pragma unroll
    for (int i = 0; i < 8; ++i)
        atomicAdd(&srep[lane * 8 + i], acc[i]);
    __syncthreads();

    int c = tid & 63;
    int r = tid >> 6;
    float4 rv = *(const float4*)&srep[c * 4];
    float4* ob = (float4*)out + c;
    for (int tt = s + r; tt < e; tt += 4)
        __stcs(ob + (size_t)tt * 64, rv);
}

extern "C" void kernel_launch(void* const* d_in, const int* in_sizes, int n_in,
                              void* d_out, int out_size) {
    const float* emb = (const float*)d_in[0];
    const float* W   = (const float*)d_in[1];
    const int*   obj = (const int*)d_in[2];
    float*       out = (float*)d_out;

    k_segmean<<<N_SEG, 256>>>(emb, obj);
    k_gemm_tanh<<<dim3(N_SEG / 64, D_DIM / 64), 256>>>(W);
    k_score_rep_bcast<<<N_SEG, 256>>>(emb, obj, out);
}

// round 5
// speedup vs baseline: 1.1719x; 1.1719x over previous
#include <cuda_runtime.h>
#include <math.h>

#define T_TOK 524288
#define D_DIM 256
#define N_SEG 8192

__device__ __align__(16) float g_mean[N_SEG * D_DIM];
__device__ __align__(16) float g_tg[N_SEG * D_DIM];
__device__ int g_segstart[N_SEG + 1];

// ---------------------------------------------------------------------------
// Pass 0: segment boundaries from sorted obj. seg_start[n] = first token with
// obj[t] >= n. Token-parallel adjacent-difference.
// ---------------------------------------------------------------------------
__global__ void k_bounds(const int* __restrict__ obj) {
    int t = blockIdx.x * blockDim.x + threadIdx.x;
    if (t >= T_TOK) return;
    if (t == 0) {
        int v0 = obj[0];
        for (int j = 0; j <= v0; ++j) g_segstart[j] = 0;
        int vl = obj[T_TOK - 1];
        for (int j = vl + 1; j <= N_SEG; ++j) g_segstart[j] = T_TOK;
    } else {
        int p = obj[t - 1], c = obj[t];
        for (int j = p + 1; j <= c; ++j) g_segstart[j] = t;
    }
}

// ---------------------------------------------------------------------------
// Pass 1: per-segment mean. One block per segment; thread owns float4 column
// (tid&63)*4 of row-group tid>>6; rows stride 4.
// ---------------------------------------------------------------------------
__global__ void __launch_bounds__(256, 6)
k_segmean(const float* __restrict__ emb) {
    int n = blockIdx.x, tid = threadIdx.x;
    __shared__ __align__(16) float red[4][256];
    int s = g_segstart[n], e = g_segstart[n + 1];

    int r = tid >> 6;
    int c4 = (tid & 63) * 4;
    const float4* base = (const float4*)emb + (c4 >> 2);

    float4 acc = make_float4(0.f, 0.f, 0.f, 0.f);
#pragma unroll 4
    for (int t = s + r; t < e; t += 4) {
        float4 v = __ldcs(base + (size_t)t * 64);
        acc.x += v.x; acc.y += v.y; acc.z += v.z; acc.w += v.w;
    }
    *(float4*)&red[r][c4] = acc;
    __syncthreads();

    float sum = red[0][tid] + red[1][tid] + red[2][tid] + red[3][tid];
    g_mean[(size_t)n * D_DIM + tid] = sum / fmaxf((float)(e - s), 1.f);
}

// ---------------------------------------------------------------------------
// Pass 2: g_tg = tanh(g_mean @ W). Tiled SGEMM, BM=BN=64, BK=16, 4x4 reg tile.
// ---------------------------------------------------------------------------
__global__ void k_gemm_tanh(const float* __restrict__ W) {
    __shared__ __align__(16) float As[16][64];
    __shared__ __align__(16) float Bs[16][64];
    int tid = threadIdx.x;
    int tx = tid & 15, ty = tid >> 4;
    int bm = blockIdx.x * 64, bn = blockIdx.y * 64;

    int ar  = tid >> 2;
    int ak4 = (tid & 3) * 4;
    int br  = tid >> 4;
    int bc4 = (tid & 15) * 4;

    float acc[4][4] = {};
    for (int k0 = 0; k0 < 256; k0 += 16) {
        float4 av = *(const float4*)(g_mean + (size_t)(bm + ar) * 256 + k0 + ak4);
        float4 bv = *(const float4*)(W + (size_t)(k0 + br) * 256 + bn + bc4);
        As[ak4 + 0][ar] = av.x;
        As[ak4 + 1][ar] = av.y;
        As[ak4 + 2][ar] = av.z;
        As[ak4 + 3][ar] = av.w;
        *(float4*)&Bs[br][bc4] = bv;
        __syncthreads();
#pragma unroll
        for (int k = 0; k < 16; ++k) {
            float a[4], b[4];
            *(float4*)a = *(const float4*)&As[k][ty * 4];
            *(float4*)b = *(const float4*)&Bs[k][tx * 4];
#pragma unroll
            for (int i = 0; i < 4; ++i)
#pragma unroll
                for (int j = 0; j < 4; ++j)
                    acc[i][j] += a[i] * b[j];
        }
        __syncthreads();
    }
#pragma unroll
    for (int i = 0; i < 4; ++i) {
        float4 o;
        o.x = tanhf(acc[i][0]);
        o.y = tanhf(acc[i][1]);
        o.z = tanhf(acc[i][2]);
        o.w = tanhf(acc[i][3]);
        *(float4*)(g_tg + (size_t)(bm + ty * 4 + i) * 256 + bn + tx * 4) = o;
    }
}

// ---------------------------------------------------------------------------
// Pass 3 (fused): scores + weighted segment sum + broadcast. One block per
// segment; warp processes two tokens per iteration.
// ---------------------------------------------------------------------------
__global__ void __launch_bounds__(256, 6)
k_score_rep_bcast(const float* __restrict__ emb, float* __restrict__ out) {
    int n = blockIdx.x, tid = threadIdx.x;
    __shared__ __align__(16) float stg[256];
    __shared__ __align__(16) float srep[256];
    int s = g_segstart[n], e = g_segstart[n + 1];
    stg[tid]  = g_tg[(size_t)n * 256 + tid];
    srep[tid] = 0.f;
    __syncthreads();
    int lane = tid & 31, w = tid >> 5;

    float4 tga = *(const float4*)&stg[lane * 8];
    float4 tgb = *(const float4*)&stg[lane * 8 + 4];
    float acc[8] = {0.f,0.f,0.f,0.f,0.f,0.f,0.f,0.f};

    const float4* base = (const float4*)emb + lane * 2;

    int t = s + 2 * w;
    for (; t + 1 < e; t += 16) {
        float4 a0 = __ldcs(base + (size_t)(t + 0) * 64);
        float4 b0 = __ldcs(base + (size_t)(t + 0) * 64 + 1);
        float4 a1 = __ldcs(base + (size_t)(t + 1) * 64);
        float4 b1 = __ldcs(base + (size_t)(t + 1) * 64 + 1);
        float d0 = a0.x*tga.x + a0.y*tga.y + a0.z*tga.z + a0.w*tga.w
                 + b0.x*tgb.x + b0.y*tgb.y + b0.z*tgb.z + b0.w*tgb.w;
        float d1 = a1.x*tga.x + a1.y*tga.y + a1.z*tga.z + a1.w*tga.w
                 + b1.x*tgb.x + b1.y*tgb.y + b1.z*tgb.z + b1.w*tgb.w;
#pragma unroll
        for (int off = 16; off; off >>= 1) {
            d0 += __shfl_xor_sync(0xffffffffu, d0, off);
            d1 += __shfl_xor_sync(0xffffffffu, d1, off);
        }
        float s0 = 1.f / (1.f + __expf(-d0));
        float s1 = 1.f / (1.f + __expf(-d1));
        acc[0] += a0.x*s0 + a1.x*s1;
        acc[1] += a0.y*s0 + a1.y*s1;
        acc[2] += a0.z*s0 + a1.z*s1;
        acc[3] += a0.w*s0 + a1.w*s1;
        acc[4] += b0.x*s0 + b1.x*s1;
        acc[5] += b0.y*s0 + b1.y*s1;
        acc[6] += b0.z*s0 + b1.z*s1;
        acc[7] += b0.w*s0 + b1.w*s1;
    }
    if (t < e) {
        float4 a0 = __ldcs(base + (size_t)t * 64);
        float4 b0 = __ldcs(base + (size_t)t * 64 + 1);
        float d0 = a0.x*tga.x + a0.y*tga.y + a0.z*tga.z + a0.w*tga.w
                 + b0.x*tgb.x + b0.y*tgb.y + b0.z*tgb.z + b0.w*tgb.w;
#pragma unroll
        for (int off = 16; off; off >>= 1)
            d0 += __shfl_xor_sync(0xffffffffu, d0, off);
        float s0 = 1.f / (1.f + __expf(-d0));
        acc[0] += a0.x*s0; acc[1] += a0.y*s0;
        acc[2] += a0.z*s0; acc[3] += a0.w*s0;
        acc[4] += b0.x*s0; acc[5] += b0.y*s0;
        acc[6] += b0.z*s0; acc[7] += b0.w*s0;
    }
#pragma unroll
    for (int i = 0; i < 8; ++i)
        atomicAdd(&srep[lane * 8 + i], acc[i]);
    __syncthreads();

    int c = tid & 63;
    int r = tid >> 6;
    float4 rv = *(const float4*)&srep[c * 4];
    float4* ob = (float4*)out + c;
    for (int tt = s + r; tt < e; tt += 4)
        __stcs(ob + (size_t)tt * 64, rv);
}

extern "C" void kernel_launch(void* const* d_in, const int* in_sizes, int n_in,
                              void* d_out, int out_size) {
    const float* emb = (const float*)d_in[0];
    const float* W   = (const float*)d_in[1];
    const int*   obj = (const int*)d_in[2];
    float*       out = (float*)d_out;

    k_bounds<<<(T_TOK + 255) / 256, 256>>>(obj);
    k_segmean<<<N_SEG, 256>>>(emb);
    k_gemm_tanh<<<dim3(N_SEG / 64, D_DIM / 64), 256>>>(W);
    k_score_rep_bcast<<<N_SEG, 256>>>(emb, out);
}